// round 15
// baseline (speedup 1.0000x reference)
#include <cuda_runtime.h>
#include <cuda_fp16.h>
#include <stdint.h>

static constexpr int Dk   = 4096;
static constexpr int Oo   = 4096;
static constexpr int Kmid = 128;
static constexpr int NTOK = 8192;
static constexpr int KSPL = 4;        // k1 K-split
static constexpr int NK1  = 16;       // K-tiles per k1 CTA (1024/64)

// Scratch (device globals — no allocation allowed)
__device__ __half g_wlowh[NTOK * Kmid];      // 2 MB   score-weighted low acts
__device__ __half g_Awh[136 * Dk];           // 1.1 MB [A(128) ; Wr(8)] fp16
__device__ __half g_Bth[Oo * Kmid];          // 1 MB   Bt[o][h*16+rr] fp16
__device__ float  g_part[256][128 * 136];    // 17.8MB deterministic k1 partials

// ---------------------------------------------------------------------------
// helpers
// ---------------------------------------------------------------------------
__device__ __forceinline__ void mma16(float* c, uint32_t a0, uint32_t a1,
                                      uint32_t a2, uint32_t a3,
                                      uint32_t b0, uint32_t b1) {
    asm volatile(
        "mma.sync.aligned.m16n8k16.row.col.f32.f16.f16.f32 "
        "{%0,%1,%2,%3}, {%4,%5,%6,%7}, {%8,%9}, {%0,%1,%2,%3};\n"
        : "+f"(c[0]), "+f"(c[1]), "+f"(c[2]), "+f"(c[3])
        : "r"(a0), "r"(a1), "r"(a2), "r"(a3), "r"(b0), "r"(b1));
}
#define LDSM4(R0, R1, R2, R3, ADDR) \
    asm volatile("ldmatrix.sync.aligned.m8n8.x4.shared.b16 {%0,%1,%2,%3}, [%4];" \
        : "=r"(R0), "=r"(R1), "=r"(R2), "=r"(R3) : "r"(ADDR))
#define LDSM2(R0, R1, ADDR) \
    asm volatile("ldmatrix.sync.aligned.m8n8.x2.shared.b16 {%0,%1}, [%2];" \
        : "=r"(R0), "=r"(R1) : "r"(ADDR))
#define CP16(dst_u32, src_ptr) \
    asm volatile("cp.async.cg.shared.global [%0], [%1], 16;\n" :: "r"(dst_u32), "l"(src_ptr))
#define CP_COMMIT() asm volatile("cp.async.commit_group;\n" ::: "memory")
#define CP_WAIT(N)  asm volatile("cp.async.wait_group %0;\n" :: "n"(N) : "memory")

// ---------------------------------------------------------------------------
// Kernel 0: convert weights to fp16 scratch (vectorized) — unchanged R14
// ---------------------------------------------------------------------------
__global__ void prep(const float* __restrict__ A, const float* __restrict__ Wr,
                     const float* __restrict__ Bm) {
    int t = (blockIdx.x * 256 + threadIdx.x) * 4;
    if (t < 136 * Dk) {
        int row = t >> 12, col = t & (Dk - 1);
        const float* src = (row < 128) ? (A + (size_t)row * Dk + col)
                                       : (Wr + (size_t)(row - 128) * Dk + col);
        float4 v = *reinterpret_cast<const float4*>(src);
        uint2 u;
        __half2 h01 = __floats2half2_rn(v.x, v.y);
        __half2 h23 = __floats2half2_rn(v.z, v.w);
        u.x = *reinterpret_cast<uint32_t*>(&h01);
        u.y = *reinterpret_cast<uint32_t*>(&h23);
        *reinterpret_cast<uint2*>(g_Awh + t) = u;
    }
    if (t < Oo * Kmid) {
        int o = t >> 7, k = t & 127;
        int h = k >> 4, rr = k & 15;
        float4 v = *reinterpret_cast<const float4*>(
            &Bm[(((size_t)h * Oo + o) << 4) + rr]);
        uint2 u;
        __half2 h01 = __floats2half2_rn(v.x, v.y);
        __half2 h23 = __floats2half2_rn(v.z, v.w);
        u.x = *reinterpret_cast<uint32_t*>(&h01);
        u.y = *reinterpret_cast<uint32_t*>(&h23);
        *reinterpret_cast<uint2*>(g_Bth + t) = u;
    }
}

// ---------------------------------------------------------------------------
// Kernel 1: partial low-GEMM (unchanged R14 — verified 43us)
// CTA = (mb: 128 tokens) x (ksplit: 1024 K); BM=128, BN=136, BK=64.
// ---------------------------------------------------------------------------
static constexpr int K1_SMEM = 36864 + 3 * 19584;   // 95616 (x2 = 191232)

__global__ __launch_bounds__(256, 2)
void k1_low(const float* __restrict__ x) {
    extern __shared__ char sm[];
    const uint32_t su = (uint32_t)__cvta_generic_to_shared(sm);
    const int tid = threadIdx.x, wid = tid >> 5, lane = tid & 31;
    const int wn = wid & 1;
    const int wm = wid >> 1;
    const int r = lane >> 2, cc = lane & 3;
    const int mb = blockIdx.x >> 2;
    const int kb0 = (blockIdx.x & 3) * 1024;

    const int aoff0 = (wm * 32 + (lane & 15)) * 144 + ((lane >> 4) << 4);
    const int aoff1 = aoff0 + 16 * 144;
    int boff[4];
#pragma unroll
    for (int p = 0; p < 4; p++)
        boff[p] = (wn * 64 + p * 16 + (lane & 7) + ((lane >> 4) << 3)) * 144
                  + (((lane >> 3) & 1) << 4);
    const int roff = (128 + (lane & 7)) * 144 + (((lane >> 3) & 1) << 4);

    float acc[2][8][4] = {};
    float racc[2][4]   = {};
    float4 rx[8];

    auto ldgx8 = [&](int s, float4* dst) {
        const float* xp = x + (size_t)mb * 128 * Dk + kb0 + s * 64;
#pragma unroll
        for (int p = 0; p < 8; p++) {
            int i = tid + p * 256, row = i >> 4, q = i & 15;
            dst[p] = *reinterpret_cast<const float4*>(xp + (size_t)row * Dk + q * 4);
        }
    };
    auto stsx8 = [&](const float4* src, int st) {
        char* xb = sm + st * 18432;
#pragma unroll
        for (int p = 0; p < 8; p++) {
            int i = tid + p * 256, row = i >> 4, q = i & 15;
            float4 v = src[p];
            __half2 h01 = __floats2half2_rn(v.x, v.y);
            __half2 h23 = __floats2half2_rn(v.z, v.w);
            uint2 u;
            u.x = *reinterpret_cast<uint32_t*>(&h01);
            u.y = *reinterpret_cast<uint32_t*>(&h23);
            *reinterpret_cast<uint2*>(xb + row * 144 + q * 8) = u;
        }
    };
    auto cpws = [&](int s, int st) {
        const __half* wp = g_Awh + kb0 + s * 64;
        uint32_t wb = su + 36864 + st * 19584;
#pragma unroll
        for (int p = 0; p < 5; p++) {
            int i = tid + p * 256;
            if (i < 1088) {
                int row = i >> 3, q = i & 7;
                CP16(wb + row * 144 + q * 16, wp + (size_t)row * Dk + q * 8);
            }
        }
    };

    ldgx8(0, rx);
    stsx8(rx, 0);
    ldgx8(1, rx);
    cpws(0, 0); CP_COMMIT();
    cpws(1, 1); CP_COMMIT();

    for (int s = 0; s < NK1; s++) {
        CP_WAIT(1);
        __syncthreads();

        if (s + 1 < NK1) stsx8(rx, (s + 1) & 1);
        if (s + 2 < NK1) { cpws(s + 2, (s + 2) % 3); ldgx8(s + 2, rx); }
        CP_COMMIT();

        const uint32_t xb = su + (s & 1) * 18432;
        const uint32_t wb = su + 36864 + (s % 3) * 19584;
#pragma unroll
        for (int ks = 0; ks < 4; ks++) {
            const int kb = ks * 32;
            uint32_t a[2][4];
            LDSM4(a[0][0], a[0][1], a[0][2], a[0][3], xb + aoff0 + kb);
            LDSM4(a[1][0], a[1][1], a[1][2], a[1][3], xb + aoff1 + kb);
#pragma unroll
            for (int p = 0; p < 4; p++) {
                uint32_t b0, b1, b2, b3;
                LDSM4(b0, b1, b2, b3, wb + boff[p] + kb);
                mma16(acc[0][2 * p],     a[0][0], a[0][1], a[0][2], a[0][3], b0, b1);
                mma16(acc[1][2 * p],     a[1][0], a[1][1], a[1][2], a[1][3], b0, b1);
                mma16(acc[0][2 * p + 1], a[0][0], a[0][1], a[0][2], a[0][3], b2, b3);
                mma16(acc[1][2 * p + 1], a[1][0], a[1][1], a[1][2], a[1][3], b2, b3);
            }
            if (wn == 0) {
                uint32_t rb0, rb1;
                LDSM2(rb0, rb1, wb + roff + kb);
                mma16(racc[0], a[0][0], a[0][1], a[0][2], a[0][3], rb0, rb1);
                mma16(racc[1], a[1][0], a[1][1], a[1][2], a[1][3], rb0, rb1);
            }
        }
    }

    float* slot = g_part[blockIdx.x];
#pragma unroll
    for (int mt = 0; mt < 2; mt++) {
        int tr = wm * 32 + mt * 16 + r;
#pragma unroll
        for (int j = 0; j < 8; j++) {
            int col = wn * 64 + j * 8 + 2 * cc;
            *reinterpret_cast<float2*>(&slot[tr * 136 + col]) =
                make_float2(acc[mt][j][0], acc[mt][j][1]);
            *reinterpret_cast<float2*>(&slot[(tr + 8) * 136 + col]) =
                make_float2(acc[mt][j][2], acc[mt][j][3]);
        }
        if (wn == 0) {
            slot[tr * 136 + 128 + 2 * cc]       = racc[mt][0];
            slot[tr * 136 + 128 + 2 * cc + 1]   = racc[mt][1];
            slot[(tr + 8) * 136 + 128 + 2 * cc]     = racc[mt][2];
            slot[(tr + 8) * 136 + 128 + 2 * cc + 1] = racc[mt][3];
        }
    }
}

// ---------------------------------------------------------------------------
// Kernel 1b: sum 4 fixed slots, softmax, write wlowh (unchanged R14)
// ---------------------------------------------------------------------------
__global__ __launch_bounds__(256)
void k1_epi(const float* __restrict__ br) {
    extern __shared__ char sme[];
    float* buf = (float*)sme;
    float* ssc = (float*)(sme + 69632);
    const int mb = blockIdx.x, tid = threadIdx.x;

    {
        const float4* p0 = reinterpret_cast<const float4*>(g_part[4 * mb + 0]);
        const float4* p1 = reinterpret_cast<const float4*>(g_part[4 * mb + 1]);
        const float4* p2 = reinterpret_cast<const float4*>(g_part[4 * mb + 2]);
        const float4* p3 = reinterpret_cast<const float4*>(g_part[4 * mb + 3]);
        float4* bo = reinterpret_cast<float4*>(buf);
        for (int e = tid; e < 128 * 136 / 4; e += 256) {
            float4 a = p0[e], b = p1[e], c = p2[e], d = p3[e];
            bo[e] = make_float4(a.x + b.x + c.x + d.x, a.y + b.y + c.y + d.y,
                                a.z + b.z + c.z + d.z, a.w + b.w + c.w + d.w);
        }
    }
    __syncthreads();
    if (tid < 128) {
        float l[8], m = -1e30f;
#pragma unroll
        for (int h = 0; h < 8; h++) {
            l[h] = buf[tid * 136 + 128 + h] + br[h];
            m = fmaxf(m, l[h]);
        }
        float s = 0.0f;
#pragma unroll
        for (int h = 0; h < 8; h++) { l[h] = __expf(l[h] - m); s += l[h]; }
        float inv = 16.0f / s;
#pragma unroll
        for (int h = 0; h < 8; h++) ssc[tid * 8 + h] = l[h] * inv;
    }
    __syncthreads();
    for (int i = tid; i < 128 * 64; i += 256) {
        int tok = i >> 6, c = (i & 63) * 2;
        float sc = ssc[tok * 8 + (c >> 4)];
        __half2 h = __floats2half2_rn(buf[tok * 136 + c] * sc,
                                      buf[tok * 136 + c + 1] * sc);
        *reinterpret_cast<__half2*>(
            &g_wlowh[(size_t)(mb * 128 + tok) * Kmid + c]) = h;
    }
}

// ---------------------------------------------------------------------------
// Kernel 2: out = wlow[8192,128] @ Bt[4096,128]^T — persistent 148 CTAs
// NEW: BM=128 x BN=256, warp tile 64x64 (8 LDSM4 per 32 HMMA, -33% L1).
// SMEM: A @0 (128*272=34816), B @34816 (2 x 256*272=69632) -> 174080; occ 1
// ---------------------------------------------------------------------------
static constexpr int TBA     = 128 * 272;           // 34816
static constexpr int TBB     = 256 * 272;           // 69632
static constexpr int K2_SMEM = TBA + 2 * TBB;       // 174080
static constexpr int NTILES  = (NTOK / 128) * (Oo / 256);   // 1024
static constexpr int GRID2   = 148;

__global__ __launch_bounds__(256, 1)
void k2_up(float* __restrict__ out) {
    extern __shared__ char sm[];
    const uint32_t su = (uint32_t)__cvta_generic_to_shared(sm);
    const int tid = threadIdx.x, wid = tid >> 5, lane = tid & 31;
    const int mw = wid >> 2;           // m half    (64 rows)
    const int nw = wid & 3;            // n quarter (64 cols)
    const int r = lane >> 2, cc = lane & 3;

    // ldmatrix per-lane byte offsets
    const int aoff0 = (mw * 64 + (lane & 15)) * 272 + ((lane >> 4) << 4);
    int boff[4];
#pragma unroll
    for (int p = 0; p < 4; p++)
        boff[p] = (nw * 64 + p * 16 + (lane & 7) + ((lane >> 4) << 3)) * 272
                  + (((lane >> 3) & 1) << 4);

    auto cp_tileA = [&](const __half* src) {
#pragma unroll
        for (int p = 0; p < 8; p++) {
            int i = tid + p * 256;
            int row = i >> 4, q = i & 15;
            CP16(su + row * 272 + q * 16, src + (size_t)row * Kmid + q * 8);
        }
    };
    auto cp_tileB = [&](const __half* src, uint32_t dst_off) {
#pragma unroll
        for (int p = 0; p < 16; p++) {
            int i = tid + p * 256;
            int row = i >> 4, q = i & 15;
            CP16(su + dst_off + row * 272 + q * 16,
                 src + (size_t)row * Kmid + q * 8);
        }
    };

    const int t0 = (blockIdx.x * NTILES) / GRID2;
    const int t1 = ((blockIdx.x + 1) * NTILES) / GRID2;
    int buf = 0, curmb = -1;

    for (int t = t0; t < t1; t++) {
        const int mb = t >> 4, nt = t & 15;
        const int m0 = mb * 128, nb = nt * 256;

        if (mb != curmb) {
            if (curmb >= 0) __syncthreads();   // all warps done reading
            cp_tileA(g_wlowh + (size_t)m0 * Kmid);
            buf = 0;
            cp_tileB(g_Bth + (size_t)nb * Kmid, (uint32_t)TBA);
            CP_COMMIT();
            curmb = mb;
        }
        CP_WAIT(0);
        __syncthreads();     // current A + B(buf) visible; prior reads of buf^1 done

        const bool nextsame = (t + 1 < t1) && (((t + 1) >> 4) == mb);
        if (nextsame) {      // prefetch next B overlaps compute + epilogue
            cp_tileB(g_Bth + (size_t)((nt + 1) * 256) * Kmid,
                     (uint32_t)(TBA + (buf ^ 1) * TBB));
            CP_COMMIT();
        }

        float acc[4][8][4] = {};
        const uint32_t ab = su;
        const uint32_t bb = su + TBA + buf * TBB;
#pragma unroll
        for (int ks = 0; ks < 8; ks++) {
            const int kb = ks * 32;
            uint32_t a[4][4];
#pragma unroll
            for (int mt = 0; mt < 4; mt++)
                LDSM4(a[mt][0], a[mt][1], a[mt][2], a[mt][3],
                      ab + aoff0 + mt * (16 * 272) + kb);
#pragma unroll
            for (int p = 0; p < 4; p++) {
                uint32_t b0, b1, b2, b3;
                LDSM4(b0, b1, b2, b3, bb + boff[p] + kb);
#pragma unroll
                for (int mt = 0; mt < 4; mt++) {
                    mma16(acc[mt][2 * p],     a[mt][0], a[mt][1], a[mt][2], a[mt][3], b0, b1);
                    mma16(acc[mt][2 * p + 1], a[mt][0], a[mt][1], a[mt][2], a[mt][3], b2, b3);
                }
            }
        }

        // epilogue: STG fp32 out (overlaps with in-flight prefetch)
#pragma unroll
        for (int mt = 0; mt < 4; mt++) {
            int row = m0 + mw * 64 + mt * 16 + r;
#pragma unroll
            for (int j = 0; j < 8; j++) {
                int col = nb + nw * 64 + j * 8 + 2 * cc;
                *reinterpret_cast<float2*>(&out[(size_t)row * Oo + col]) =
                    make_float2(acc[mt][j][0], acc[mt][j][1]);
                *reinterpret_cast<float2*>(&out[(size_t)(row + 8) * Oo + col]) =
                    make_float2(acc[mt][j][2], acc[mt][j][3]);
            }
        }
        if (nextsame) buf ^= 1;
    }
}

// ---------------------------------------------------------------------------
extern "C" void kernel_launch(void* const* d_in, const int* in_sizes, int n_in,
                              void* d_out, int out_size) {
    const float* x  = (const float*)d_in[0];
    const float* A  = (const float*)d_in[1];
    const float* Bm = (const float*)d_in[2];
    const float* Wr = (const float*)d_in[3];
    const float* br = (const float*)d_in[4];
    float* out = (float*)d_out;

    cudaFuncSetAttribute(k1_low, cudaFuncAttributeMaxDynamicSharedMemorySize, K1_SMEM);
    cudaFuncSetAttribute(k1_epi, cudaFuncAttributeMaxDynamicSharedMemorySize, 73728);
    cudaFuncSetAttribute(k2_up,  cudaFuncAttributeMaxDynamicSharedMemorySize, K2_SMEM);

    prep<<<136 * Dk / 4 / 256, 256>>>(A, Wr, Bm);
    k1_low<<<64 * KSPL, 256, K1_SMEM>>>(x);
    k1_epi<<<NTOK / 128, 256, 73728>>>(br);
    k2_up<<<GRID2, 256, K2_SMEM>>>(out);
}